// round 12
// baseline (speedup 1.0000x reference)
#include <cuda_runtime.h>
#include <cstdint>

#define BB 32
#define NN 16384
#define DD 64

// Scratch (no allocations allowed)
__device__ uint32_t g_keys[BB * NN];             // 2MB monotonic keys
__device__ float    g_tokensum[BB * NN];         // 2MB per-token score sums

// ---------------------------------------------------------------------------
// k_fused: heterogeneous grid. 512 key-CTAs (g%5==0) compute ws keys
// (4 elems/thread, float4 I/O); 2048 sum-CTAs stream score into per-token
// sums (thread per token, 16x LDG.128). Key math hides in the streaming
// kernel's idle issue slots.
// ---------------------------------------------------------------------------
__global__ void __launch_bounds__(256) k_fused(
    const float* __restrict__ u_g, const float* __restrict__ lpt,
    const float* __restrict__ lph, const float* __restrict__ lpw,
    const float* __restrict__ score, float* __restrict__ out, int out_size)
{
    int g = blockIdx.x;
    if (g % 5 == 0) {
        // ---- keys: keysId in [0, 512) ----
        int tid4 = (g / 5) * 256 + threadIdx.x;
        if (tid4 == 0 && out_size != BB * NN) out[0] = 0.f;  // init loss slot
        int idx = tid4 * 4;                  // 4 consecutive elements
        int b = idx >> 14;
        int n = idx & (NN - 1);
        int t = n >> 10;
        int h = (n >> 5) & 31;
        int w = n & 31;                      // multiple of 4; same t/h for all

        float4 u = *(const float4*)(u_g + idx);
        float4 lw = *(const float4*)(lpw + b * 32 + w);
        float base = lpt[b * 16 + t] + lph[b * 32 + h];

        float g0 = -logf(-logf(u.x));
        float g1 = -logf(-logf(u.y));
        float g2 = -logf(-logf(u.z));
        float g3 = -logf(-logf(u.w));
        float ws0 = g0 + (base + lw.x);      // (lpt+lph)+lpw == ref association
        float ws1 = g1 + (base + lw.y);
        float ws2 = g2 + (base + lw.z);
        float ws3 = g3 + (base + lw.w);
        uint32_t b0 = __float_as_uint(ws0), b1 = __float_as_uint(ws1);
        uint32_t b2 = __float_as_uint(ws2), b3 = __float_as_uint(ws3);
        uint4 ok;
        ok.x = (b0 & 0x80000000u) ? ~b0 : (b0 | 0x80000000u);
        ok.y = (b1 & 0x80000000u) ? ~b1 : (b1 | 0x80000000u);
        ok.z = (b2 & 0x80000000u) ? ~b2 : (b2 | 0x80000000u);
        ok.w = (b3 & 0x80000000u) ? ~b3 : (b3 | 0x80000000u);
        *(uint4*)(g_keys + idx) = ok;
    } else {
        // ---- tokensum: sumId in [0, 2048) ----
        int sumId = g - g / 5 - 1;
        int tok = sumId * 256 + threadIdx.x;
        const float4* __restrict__ p = (const float4*)(score + ((size_t)tok << 6));
        float a0 = 0.f, a1 = 0.f, a2 = 0.f, a3 = 0.f;
        #pragma unroll
        for (int j = 0; j < 16; j += 4) {
            float4 v0 = p[j + 0], v1 = p[j + 1], v2 = p[j + 2], v3 = p[j + 3];
            a0 += (v0.x + v0.y) + (v0.z + v0.w);
            a1 += (v1.x + v1.y) + (v1.z + v1.w);
            a2 += (v2.x + v2.y) + (v2.z + v2.w);
            a3 += (v3.x + v3.y) + (v3.z + v3.w);
        }
        g_tokensum[tok] = (a0 + a1) + (a2 + a3);
    }
}

// ---------------------------------------------------------------------------
// k_select_loss: one CTA per row. Register keys + smem shadow; exact 4x8-bit
// radix select; per-token visibility; writes visible floats; reduces
// vis-masked tokensums to the rate-corrected loss (atomicAdd across 32 CTAs).
// ---------------------------------------------------------------------------
__global__ void __launch_bounds__(1024, 1) k_select_loss(
    const float* __restrict__ u_k, float* __restrict__ out, int out_size)
{
    extern __shared__ uint32_t skeys[];   // NN words (64KB), rare tie path
    __shared__ unsigned hist[256];
    __shared__ unsigned suf[256];
    __shared__ uint32_t s_prefix;
    __shared__ int s_krem, s_eqcnt;
    __shared__ float ssum[32];

    int b = blockIdx.x;
    int tid = threadIdx.x;

    // k per row: rates = (u_k + b/31) % 1 ; k = clip(int(N*rates), 1, N-1)
    float r = u_k[0] + (float)b * (1.0f / 31.0f);
    r = r - floorf(r);
    int k = (int)(16384.0f * r);
    k = k < 1 ? 1 : (k > NN - 1 ? NN - 1 : k);

    const uint32_t* __restrict__ keys = g_keys + ((size_t)b << 14);
    uint32_t key[16];
    #pragma unroll
    for (int s = 0; s < 16; s++) {
        uint32_t kk = keys[s * 1024 + tid];
        key[s] = kk;
        skeys[s * 1024 + tid] = kk;
    }
    __syncthreads();

    uint32_t prefix = 0, pmask = 0;
    int krem = k;
    for (int pass = 0; pass < 4; pass++) {
        int shift = 24 - 8 * pass;
        if (tid < 256) hist[tid] = 0;
        __syncthreads();
        #pragma unroll
        for (int s = 0; s < 16; s++) {
            uint32_t kk = key[s];
            if ((kk & pmask) == prefix)
                atomicAdd(&hist[(kk >> shift) & 255u], 1u);
        }
        __syncthreads();
        if (tid < 256) suf[tid] = hist[tid];
        __syncthreads();
        for (int d = 1; d < 256; d <<= 1) {       // inclusive suffix sums
            unsigned v = 0;
            if (tid < 256) { v = suf[tid]; if (tid + d < 256) v += suf[tid + d]; }
            __syncthreads();
            if (tid < 256) suf[tid] = v;
            __syncthreads();
        }
        if (tid < 256) {
            int above = (int)(suf[tid] - hist[tid]);   // strictly larger keys
            if (above < krem && krem <= (int)suf[tid]) {
                s_prefix = prefix | ((uint32_t)tid << shift);
                s_krem = krem - above;
                if (pass == 3) s_eqcnt = (int)hist[tid];
            }
        }
        __syncthreads();
        prefix = s_prefix;
        krem = s_krem;
        pmask |= (0xFFu << shift);
        __syncthreads();
    }

    uint32_t thr = prefix;
    int eqcnt = s_eqcnt;

    bool emit_vis = (out_size >= BB * NN);
    int vis_off = (out_size > BB * NN) ? 1 : 0;      // loss slot first
    float* __restrict__ out_vis = out + vis_off + ((size_t)b << 14);
    const float* __restrict__ ts = g_tokensum + ((size_t)b << 14);

    float acc = 0.f;
    #pragma unroll
    for (int s = 0; s < 16; s++) {
        uint32_t kk = key[s];
        bool vis;
        if (kk > thr) vis = true;
        else if (kk < thr) vis = false;
        else if (eqcnt <= krem) vis = true;          // all ties fit in top-k
        else {
            // rare tie path: stable rank by index among equals (from smem)
            int n = s * 1024 + tid;
            int cnt = 0;
            for (int i = 0; i < n; i++) cnt += (skeys[i] == thr);
            vis = cnt < krem;
        }
        int n = s * 1024 + tid;
        if (emit_vis) out_vis[n] = vis ? 1.0f : 0.0f;
        if (!vis) acc += ts[n];
    }

    // block reduction (1024 threads) -> loss contribution
    int lane = tid & 31, warp = tid >> 5;
    #pragma unroll
    for (int o = 16; o; o >>= 1) acc += __shfl_down_sync(0xffffffffu, acc, o);
    if (lane == 0) ssum[warp] = acc;
    __syncthreads();
    if (warp == 0) {
        float v = ssum[lane];
        #pragma unroll
        for (int o = 16; o; o >>= 1) v += __shfl_down_sync(0xffffffffu, v, o);
        if (tid == 0 && out_size != BB * NN) {
            float w = v * (16384.0f / (float)(NN - k));
            atomicAdd(out, w / 33554432.0f);          // B*N*D
        }
    }
}

extern "C" void kernel_launch(void* const* d_in, const int* in_sizes, int n_in,
                              void* d_out, int out_size) {
    const float* u_g   = (const float*)d_in[0];
    const float* lpt   = (const float*)d_in[1];
    const float* lph   = (const float*)d_in[2];
    const float* lpw   = (const float*)d_in[3];
    const float* u_k   = (const float*)d_in[4];
    const float* score = (const float*)d_in[5];
    float* out = (float*)d_out;

    cudaFuncSetAttribute(k_select_loss,
                         cudaFuncAttributeMaxDynamicSharedMemorySize, 65536);

    k_fused<<<2560, 256>>>(u_g, lpt, lph, lpw, score, out, out_size);
    k_select_loss<<<BB, 1024, 65536>>>(u_k, out, out_size);
}

// round 13
// speedup vs baseline: 1.9892x; 1.9892x over previous
#include <cuda_runtime.h>
#include <cstdint>

#define BB 32
#define NN 16384
#define DD 64

// Scratch (no allocations allowed)
__device__ uint32_t g_keys[BB * NN];             // 2MB monotonic keys
__device__ float    g_rowsum[BB];
__device__ int      g_k[BB];
__device__ unsigned g_visbits[BB * (NN / 32)];   // 64KB visibility bitmask
__device__ unsigned g_done;

// Hybrid gumbel: fast MUFU logs everywhere except the cancellation zone
// (u -> 1, inner log -> 0) where the outer log amplifies inner error; there
// we recompute with accurate logf (bit-matches the proven-correct path).
__device__ __forceinline__ float gumbel_hybrid(float u) {
    float y = -__logf(u);
    if (y >= 0.01f) {
        return -__logf(y);                   // abs err ~1e-5 worst-case here
    } else {
        return -logf(-logf(u));              // accurate slow path (~1% of u)
    }
}

// ---------------------------------------------------------------------------
// k_keys: full-chip key computation, 2 elems/thread, hybrid-precision logs.
// ---------------------------------------------------------------------------
__global__ void __launch_bounds__(256) k_keys(
    const float* __restrict__ u_g, const float* __restrict__ lpt,
    const float* __restrict__ lph, const float* __restrict__ lpw)
{
    int tid2 = blockIdx.x * 256 + threadIdx.x;
    if (tid2 < BB) g_rowsum[tid2] = 0.f;
    if (tid2 == 0) g_done = 0u;
    int idx = tid2 * 2;
    int b = idx >> 14;
    int n = idx & (NN - 1);
    int t = n >> 10;
    int h = (n >> 5) & 31;
    int w = n & 31;                          // even; w,w+1 share t/h

    float2 u = *(const float2*)(u_g + idx);
    float2 lw = *(const float2*)(lpw + b * 32 + w);
    float base = lpt[b * 16 + t] + lph[b * 32 + h];

    float g0 = gumbel_hybrid(u.x);
    float g1 = gumbel_hybrid(u.y);
    float ws0 = g0 + (base + lw.x);          // (lpt+lph)+lpw == ref association
    float ws1 = g1 + (base + lw.y);
    uint32_t b0 = __float_as_uint(ws0);
    uint32_t b1 = __float_as_uint(ws1);
    uint2 outk;
    outk.x = (b0 & 0x80000000u) ? ~b0 : (b0 | 0x80000000u);
    outk.y = (b1 & 0x80000000u) ? ~b1 : (b1 | 0x80000000u);
    *(uint2*)(g_keys + idx) = outk;
}

// ---------------------------------------------------------------------------
// k_select: one CTA per row; register keys + smem shadow; exact 4x8-bit
// radix select; emits visibility bitmask.
// ---------------------------------------------------------------------------
__global__ void __launch_bounds__(1024, 1) k_select(const float* __restrict__ u_k)
{
    extern __shared__ uint32_t skeys[];   // NN words (64KB)
    __shared__ unsigned hist[256];
    __shared__ unsigned suf[256];
    __shared__ uint32_t s_prefix;
    __shared__ int s_krem, s_eqcnt;

    int b = blockIdx.x;
    int tid = threadIdx.x;

    // k per row: rates = (u_k + b/31) % 1 ; k = clip(int(N*rates), 1, N-1)
    float r = u_k[0] + (float)b * (1.0f / 31.0f);
    r = r - floorf(r);
    int k = (int)(16384.0f * r);
    k = k < 1 ? 1 : (k > NN - 1 ? NN - 1 : k);
    if (tid == 0) g_k[b] = k;

    const uint32_t* __restrict__ keys = g_keys + ((size_t)b << 14);
    uint32_t key[16];
    #pragma unroll
    for (int s = 0; s < 16; s++) {
        uint32_t kk = keys[s * 1024 + tid];
        key[s] = kk;
        skeys[s * 1024 + tid] = kk;
    }
    __syncthreads();

    uint32_t prefix = 0, pmask = 0;
    int krem = k;
    for (int pass = 0; pass < 4; pass++) {
        int shift = 24 - 8 * pass;
        if (tid < 256) hist[tid] = 0;
        __syncthreads();
        #pragma unroll
        for (int s = 0; s < 16; s++) {
            uint32_t kk = key[s];
            if ((kk & pmask) == prefix)
                atomicAdd(&hist[(kk >> shift) & 255u], 1u);
        }
        __syncthreads();
        if (tid < 256) suf[tid] = hist[tid];
        __syncthreads();
        for (int d = 1; d < 256; d <<= 1) {       // inclusive suffix sums
            unsigned v = 0;
            if (tid < 256) { v = suf[tid]; if (tid + d < 256) v += suf[tid + d]; }
            __syncthreads();
            if (tid < 256) suf[tid] = v;
            __syncthreads();
        }
        if (tid < 256) {
            int above = (int)(suf[tid] - hist[tid]);
            if (above < krem && krem <= (int)suf[tid]) {
                s_prefix = prefix | ((uint32_t)tid << shift);
                s_krem = krem - above;
                if (pass == 3) s_eqcnt = (int)hist[tid];
            }
        }
        __syncthreads();
        prefix = s_prefix;
        krem = s_krem;
        pmask |= (0xFFu << shift);
        __syncthreads();
    }

    uint32_t thr = prefix;
    int eqcnt = s_eqcnt;

    #pragma unroll
    for (int s = 0; s < 16; s++) {
        uint32_t kk = key[s];
        bool vis;
        if (kk > thr) vis = true;
        else if (kk < thr) vis = false;
        else if (eqcnt <= krem) vis = true;
        else {
            int n = s * 1024 + tid;
            int cnt = 0;
            for (int i = 0; i < n; i++) cnt += (skeys[i] == thr);
            vis = cnt < krem;
        }
        unsigned m = __ballot_sync(0xffffffffu, vis);
        if ((tid & 31) == 0)
            g_visbits[(b << 9) + ((s * 1024 + tid) >> 5)] = m;
    }
}

// ---------------------------------------------------------------------------
// k_mask_final: half-warp float4 predicated gather (best measured shape),
// blocks round-robin over rows, last block emits the loss.
// ---------------------------------------------------------------------------
__global__ void __launch_bounds__(256) k_mask_final(
    const float* __restrict__ score, float* __restrict__ out, int out_size)
{
    __shared__ float ssum[8];
    __shared__ bool slast;
    int g = blockIdx.x;
    int b = g & 31;
    int chunk = g >> 5;
    int warp = threadIdx.x >> 5, lane = threadIdx.x & 31;
    int tok0 = (b << 14) + chunk * 256 + warp * 32;

    unsigned visword = g_visbits[tok0 >> 5];

    if (out_size >= BB * NN) {
        int off = (out_size > BB * NN) ? 1 : 0;      // loss slot first
        out[off + tok0 + lane] = ((visword >> lane) & 1u) ? 1.0f : 0.0f;
    }

    int sub = lane >> 4;
    const float4* __restrict__ rowsq =
        (const float4*)score + (((size_t)(tok0 + sub)) << 4) + (lane & 15);

    float a0 = 0.f, a1 = 0.f, a2 = 0.f, a3 = 0.f;
    #pragma unroll
    for (int jj = 0; jj < 16; jj += 4) {
        float4 z = make_float4(0.f, 0.f, 0.f, 0.f);
        float4 v0 = z, v1 = z, v2 = z, v3 = z;
        if (!((visword >> (2 * (jj + 0) + sub)) & 1u)) v0 = rowsq[(jj + 0) * 32];
        if (!((visword >> (2 * (jj + 1) + sub)) & 1u)) v1 = rowsq[(jj + 1) * 32];
        if (!((visword >> (2 * (jj + 2) + sub)) & 1u)) v2 = rowsq[(jj + 2) * 32];
        if (!((visword >> (2 * (jj + 3) + sub)) & 1u)) v3 = rowsq[(jj + 3) * 32];
        a0 += (v0.x + v0.y) + (v0.z + v0.w);
        a1 += (v1.x + v1.y) + (v1.z + v1.w);
        a2 += (v2.x + v2.y) + (v2.z + v2.w);
        a3 += (v3.x + v3.y) + (v3.z + v3.w);
    }
    float acc = (a0 + a1) + (a2 + a3);
    #pragma unroll
    for (int o = 16; o; o >>= 1) acc += __shfl_down_sync(0xffffffffu, acc, o);
    if (lane == 0) ssum[warp] = acc;
    __syncthreads();
    if (threadIdx.x == 0) {
        float t = 0.f;
        #pragma unroll
        for (int i = 0; i < 8; i++) t += ssum[i];
        atomicAdd(&g_rowsum[b], t);
        __threadfence();
        unsigned old = atomicAdd(&g_done, 1u);
        slast = (old == gridDim.x - 1);
    }
    __syncthreads();
    if (slast && threadIdx.x < 32) {
        __threadfence();
        float w = g_rowsum[threadIdx.x] *
                  (16384.0f / (float)(NN - g_k[threadIdx.x]));
        #pragma unroll
        for (int o = 16; o; o >>= 1) w += __shfl_down_sync(0xffffffffu, w, o);
        if (threadIdx.x == 0 && out_size != BB * NN)
            out[0] = w / 33554432.0f;                // B*N*D
    }
}

extern "C" void kernel_launch(void* const* d_in, const int* in_sizes, int n_in,
                              void* d_out, int out_size) {
    const float* u_g   = (const float*)d_in[0];
    const float* lpt   = (const float*)d_in[1];
    const float* lph   = (const float*)d_in[2];
    const float* lpw   = (const float*)d_in[3];
    const float* u_k   = (const float*)d_in[4];
    const float* score = (const float*)d_in[5];
    float* out = (float*)d_out;

    cudaFuncSetAttribute(k_select,
                         cudaFuncAttributeMaxDynamicSharedMemorySize, 65536);

    k_keys<<<BB * NN / 512, 256>>>(u_g, lpt, lph, lpw);
    k_select<<<BB, 1024, 65536>>>(u_k);
    k_mask_final<<<BB * NN / 256, 256>>>(score, out, out_size);
}